// round 12
// baseline (speedup 1.0000x reference)
#include <cuda_runtime.h>

// IFOPooling: h_t = f_t * h_{t-1} + i_t * z_t over seq (last dim, contiguous).
// [B=16, H=1024, S=2048] fp32 -> 16384 rows of 2048.
//
// FINAL (R6 + .nc loads): block-per-row, TPB=256, EPT=8, Blackwell 256-bit
// global accesses. Loads use the non-coherent read-only path (inputs are
// immutable) + evict_first; store is evict_first. Three-phase affine scan:
//   segment composite: h_out = F*h_in + X;  (F1,X1)∘(F2,X2) = (F1F2, F2X1+X2)
// Champion measured 72.9-73.0 us kernel @ 7.03 TB/s (88.7% DRAM), traffic at
// the exact 512.5 MB minimum. Ten structural variants all inferior.

#define SEQ 2048
#define TPB 256
#define EPT 8   // elements per thread

// 256-bit non-coherent global load: 8 floats, ptr 32B-aligned, read-only data.
__device__ __forceinline__ void ldg256(const float* p, float r[8]) {
    asm volatile(
        "ld.global.nc.L1::evict_first.v8.f32 {%0,%1,%2,%3,%4,%5,%6,%7}, [%8];"
        : "=f"(r[0]), "=f"(r[1]), "=f"(r[2]), "=f"(r[3]),
          "=f"(r[4]), "=f"(r[5]), "=f"(r[6]), "=f"(r[7])
        : "l"(p));
}

// 256-bit global store: 8 floats, ptr must be 32B-aligned.
__device__ __forceinline__ void stg256(float* p, const float r[8]) {
    asm volatile(
        "st.global.L1::evict_first.v8.f32 [%0], {%1,%2,%3,%4,%5,%6,%7,%8};"
        :: "l"(p),
           "f"(r[0]), "f"(r[1]), "f"(r[2]), "f"(r[3]),
           "f"(r[4]), "f"(r[5]), "f"(r[6]), "f"(r[7])
        : "memory");
}

__global__ __launch_bounds__(TPB, 6) void ifo_scan_kernel(
    const float* __restrict__ f,
    const float* __restrict__ z,
    const float* __restrict__ ig,
    float* __restrict__ out)
{
    const int row  = blockIdx.x;
    const int base = row * SEQ;
    const int t    = threadIdx.x;
    const int off  = base + t * EPT;

    // ---- Phase 1: 3 front-batched 256-bit loads ----
    float fv[EPT], zv[EPT], iv[EPT];
    ldg256(f  + off, fv);
    ldg256(z  + off, zv);
    ldg256(ig + off, iv);

    float xv[EPT];
    #pragma unroll
    for (int j = 0; j < EPT; j++) xv[j] = iv[j] * zv[j];

    // local segment composite (F, X): h_out = F*h_in + X
    float F = 1.0f, X = 0.0f;
    #pragma unroll
    for (int j = 0; j < EPT; j++) {
        X = fmaf(fv[j], X, xv[j]);
        F *= fv[j];
    }

    // ---- Phase 2: inclusive warp scan of composites ----
    const unsigned lane = t & 31u;
    const unsigned warp = t >> 5;
    float Fs = F, Xs = X;
    #pragma unroll
    for (int d = 1; d < 32; d <<= 1) {
        float Fo = __shfl_up_sync(0xFFFFFFFFu, Fs, d);
        float Xo = __shfl_up_sync(0xFFFFFFFFu, Xs, d);
        if (lane >= (unsigned)d) {
            Xs = fmaf(Fs, Xo, Xs);   // (Fo,Xo) then (Fs,Xs)
            Fs = Fs * Fo;
        }
    }

    // warp aggregates -> smem (8 warps)
    __shared__ float sF[TPB / 32];
    __shared__ float sX[TPB / 32];
    if (lane == 31) { sF[warp] = Fs; sX[warp] = Xs; }
    __syncthreads();

    // carry from preceding warps (<= 7 fmas)
    float Xc = 0.0f;
    #pragma unroll
    for (int w = 0; w < TPB / 32; w++) {
        if (w < (int)warp) Xc = fmaf(sF[w], Xc, sX[w]);
    }

    // exclusive-within-warp composite = inclusive of lane-1
    float Fex = __shfl_up_sync(0xFFFFFFFFu, Fs, 1);
    float Xex = __shfl_up_sync(0xFFFFFFFFu, Xs, 1);
    if (lane == 0) { Fex = 1.0f; Xex = 0.0f; }

    float h = fmaf(Fex, Xc, Xex);

    // ---- Phase 3: replay from registers, one 256-bit store ----
    float r[EPT];
    #pragma unroll
    for (int j = 0; j < EPT; j++) {
        h = fmaf(fv[j], h, xv[j]);
        r[j] = h;
    }
    stg256(out + off, r);
}

extern "C" void kernel_launch(void* const* d_in, const int* in_sizes, int n_in,
                              void* d_out, int out_size)
{
    const float* f  = (const float*)d_in[0];
    const float* z  = (const float*)d_in[1];
    const float* ig = (const float*)d_in[2];
    float* out = (float*)d_out;

    const int rows = out_size / SEQ;   // 16384
    ifo_scan_kernel<<<rows, TPB>>>(f, z, ig, out);
}

// round 13
// speedup vs baseline: 1.0086x; 1.0086x over previous
#include <cuda_runtime.h>

// IFOPooling: h_t = f_t * h_{t-1} + i_t * z_t over seq (last dim, contiguous).
// [B=16, H=1024, S=2048] fp32 -> 16384 rows of 2048.
//
// FINAL (R6 + .nc loads): block-per-row, TPB=256, EPT=8, Blackwell 256-bit
// global accesses. Loads use the non-coherent read-only path (inputs are
// immutable) + evict_first; store is evict_first. Three-phase affine scan:
//   segment composite: h_out = F*h_in + X;  (F1,X1)∘(F2,X2) = (F1F2, F2X1+X2)
// Champion measured 72.9-73.0 us kernel @ 7.03 TB/s (88.7% DRAM), traffic at
// the exact 512.5 MB minimum. Ten structural variants all inferior.

#define SEQ 2048
#define TPB 256
#define EPT 8   // elements per thread

// 256-bit non-coherent global load: 8 floats, ptr 32B-aligned, read-only data.
__device__ __forceinline__ void ldg256(const float* p, float r[8]) {
    asm volatile(
        "ld.global.nc.L1::evict_first.v8.f32 {%0,%1,%2,%3,%4,%5,%6,%7}, [%8];"
        : "=f"(r[0]), "=f"(r[1]), "=f"(r[2]), "=f"(r[3]),
          "=f"(r[4]), "=f"(r[5]), "=f"(r[6]), "=f"(r[7])
        : "l"(p));
}

// 256-bit global store: 8 floats, ptr must be 32B-aligned.
__device__ __forceinline__ void stg256(float* p, const float r[8]) {
    asm volatile(
        "st.global.L1::evict_first.v8.f32 [%0], {%1,%2,%3,%4,%5,%6,%7,%8};"
        :: "l"(p),
           "f"(r[0]), "f"(r[1]), "f"(r[2]), "f"(r[3]),
           "f"(r[4]), "f"(r[5]), "f"(r[6]), "f"(r[7])
        : "memory");
}

__global__ __launch_bounds__(TPB, 6) void ifo_scan_kernel(
    const float* __restrict__ f,
    const float* __restrict__ z,
    const float* __restrict__ ig,
    float* __restrict__ out)
{
    const int row  = blockIdx.x;
    const int base = row * SEQ;
    const int t    = threadIdx.x;
    const int off  = base + t * EPT;

    // ---- Phase 1: 3 front-batched 256-bit loads ----
    float fv[EPT], zv[EPT], iv[EPT];
    ldg256(f  + off, fv);
    ldg256(z  + off, zv);
    ldg256(ig + off, iv);

    float xv[EPT];
    #pragma unroll
    for (int j = 0; j < EPT; j++) xv[j] = iv[j] * zv[j];

    // local segment composite (F, X): h_out = F*h_in + X
    float F = 1.0f, X = 0.0f;
    #pragma unroll
    for (int j = 0; j < EPT; j++) {
        X = fmaf(fv[j], X, xv[j]);
        F *= fv[j];
    }

    // ---- Phase 2: inclusive warp scan of composites ----
    const unsigned lane = t & 31u;
    const unsigned warp = t >> 5;
    float Fs = F, Xs = X;
    #pragma unroll
    for (int d = 1; d < 32; d <<= 1) {
        float Fo = __shfl_up_sync(0xFFFFFFFFu, Fs, d);
        float Xo = __shfl_up_sync(0xFFFFFFFFu, Xs, d);
        if (lane >= (unsigned)d) {
            Xs = fmaf(Fs, Xo, Xs);   // (Fo,Xo) then (Fs,Xs)
            Fs = Fs * Fo;
        }
    }

    // warp aggregates -> smem (8 warps)
    __shared__ float sF[TPB / 32];
    __shared__ float sX[TPB / 32];
    if (lane == 31) { sF[warp] = Fs; sX[warp] = Xs; }
    __syncthreads();

    // carry from preceding warps (<= 7 fmas)
    float Xc = 0.0f;
    #pragma unroll
    for (int w = 0; w < TPB / 32; w++) {
        if (w < (int)warp) Xc = fmaf(sF[w], Xc, sX[w]);
    }

    // exclusive-within-warp composite = inclusive of lane-1
    float Fex = __shfl_up_sync(0xFFFFFFFFu, Fs, 1);
    float Xex = __shfl_up_sync(0xFFFFFFFFu, Xs, 1);
    if (lane == 0) { Fex = 1.0f; Xex = 0.0f; }

    float h = fmaf(Fex, Xc, Xex);

    // ---- Phase 3: replay from registers, one 256-bit store ----
    float r[EPT];
    #pragma unroll
    for (int j = 0; j < EPT; j++) {
        h = fmaf(fv[j], h, xv[j]);
        r[j] = h;
    }
    stg256(out + off, r);
}

extern "C" void kernel_launch(void* const* d_in, const int* in_sizes, int n_in,
                              void* d_out, int out_size)
{
    const float* f  = (const float*)d_in[0];
    const float* z  = (const float*)d_in[1];
    const float* ig = (const float*)d_in[2];
    float* out = (float*)d_out;

    const int rows = out_size / SEQ;   // 16384
    ifo_scan_kernel<<<rows, TPB>>>(f, z, ig, out);
}